// round 11
// baseline (speedup 1.0000x reference)
#include <cuda_runtime.h>
#include <math.h>

// Problem constants
#define B    64
#define SEQ  512
#define H    1024
#define OUTD 128

// Recurrence config (R9-proven partition)
#define G    128           // persistent CTAs (<=148 SMs => co-resident, 1/SM)
#define CPC  8             // columns of W_hh per CTA (H / G)
#define NT   512           // 16 warps -> 4 per SMSP
#define NW   16
#define KC   (H / NW)      // 64 k per warp (lane k-parity -> 32 iters)
#define NSLOT (2 * NW)     // 32 partial slots (warp x k-parity)
#define SLOTSTRIDE 577     // 64*9 + 1 pad (float stores only)

static_assert(G * CPC == H, "partition");

typedef unsigned long long u64;

// Scratch (device globals: allocation-free rule). Zero-initialized at load.
__device__ float g_hs[(size_t)SEQ * H * B];  // hidden states [t][h][b]
__device__ float g_h0[H * B];                // initial h = 0 (never written)
__device__ __align__(16) unsigned g_flag[G]; // per-CTA monotonic step counters

// ---------------------------------------------------------------------------
// Packed f32x2 helpers (Blackwell FFMA2)
// ---------------------------------------------------------------------------
__device__ __forceinline__ u64 dup2(float x) {
    u64 r; unsigned u = __float_as_uint(x);
    asm("mov.b64 %0, {%1, %2};" : "=l"(r) : "r"(u), "r"(u));
    return r;
}
__device__ __forceinline__ void ffma2(u64& d, u64 a, u64 b) {
    asm("fma.rn.f32x2 %0, %1, %2, %3;" : "=l"(d) : "l"(a), "l"(b), "l"(d));
}
__device__ __forceinline__ void unpack2(u64 v, float& x, float& y) {
    unsigned lo, hi;
    asm("mov.b64 {%0, %1}, %2;" : "=r"(lo), "=r"(hi) : "l"(v));
    x = __uint_as_float(lo); y = __uint_as_float(hi);
}

__device__ __forceinline__ float tanh_safe(float x) {
    float ax = fabsf(x);
    float e  = __expf(2.0f * ax);
    float r  = 1.0f - 2.0f / (e + 1.0f);
    return copysignf(r, x);
}

// Release-store this CTA's flag; acquire-load 4 flags (vector).
__device__ __forceinline__ void st_rel(unsigned* p, unsigned v) {
    asm volatile("st.release.gpu.global.u32 [%0], %1;" :: "l"(p), "r"(v) : "memory");
}
__device__ __forceinline__ uint4 ld_acq4(const unsigned* p) {
    uint4 v;
    asm volatile("ld.acquire.gpu.global.v4.u32 {%0,%1,%2,%3}, [%4];"
                 : "=r"(v.x), "=r"(v.y), "=r"(v.z), "=r"(v.w) : "l"(p) : "memory");
    return v;
}

// ---------------------------------------------------------------------------
// Atomic-free grid barrier. Arrive: store-release own flag = t+1 (no RMW, no
// contention). Wait: warp 0 polls all 128 flags (1 ld.acquire.v4 per lane),
// ballots, then __syncthreads releases the CTA. Valid: 128 CTAs co-resident.
// Monotonic flags within a launch; reset kernel zeroes them per launch.
// ---------------------------------------------------------------------------
__device__ __forceinline__ void grid_sync_flags(int bid, unsigned tgt) {
    __syncthreads();                         // all g_hs writes done CTA-wide
    if (threadIdx.x == 0) st_rel(&g_flag[bid], tgt);
    if (threadIdx.x < 32) {
        const unsigned* fp = g_flag + threadIdx.x * 4;
        while (true) {
            uint4 v = ld_acq4(fp);
            unsigned mn = min(min(v.x, v.y), min(v.z, v.w));
            if (__all_sync(0xFFFFFFFFu, mn >= tgt)) break;
        }
    }
    __syncthreads();                         // propagate release to all warps
}

// ---------------------------------------------------------------------------
// Reset flags each launch so graph replays start from zero.
// ---------------------------------------------------------------------------
__global__ void rnn_reset_kernel() {
    if (threadIdx.x < G) g_flag[threadIdx.x] = 0u;
}

// ---------------------------------------------------------------------------
// Persistent recurrence: h_t = tanh(h_{t-1} @ W_hh + W_xh[X[:,t]] + b_h)
// CTA c owns columns [c*8, c*8+8); W slice resident in smem all 512 steps.
// 16 warps split k (64 each); lane k-parity halves again. Lane tile 4b x 8j.
// ---------------------------------------------------------------------------
__global__ void __launch_bounds__(NT, 1)
rnn_recurrence_kernel(const int* __restrict__ X,
                      const float* __restrict__ W_hh,
                      const float* __restrict__ W_xh,
                      const float* __restrict__ b_h) {
    extern __shared__ float sm[];
    float* ws  = sm;                       // [H][CPC]    32 KB
    float* red = sm + H * CPC;             // [32][577]   ~72 KB

    const int tid = threadIdx.x;
    const int bid = blockIdx.x;
    const int c0  = bid * CPC;

    // One-time W_hh slice load (k-major rows of 8 columns)
    for (int i = tid; i < H * CPC; i += NT) {
        int k = i >> 3, j = i & 7;
        ws[i] = W_hh[(size_t)k * H + c0 + j];
    }

    const int w    = tid >> 5;
    const int lane = tid & 31;
    const int b4   = lane & 15;       // 4-batch group
    const int kpar = lane >> 4;       // k parity within warp
    const int bb0  = b4 * 4;
    const int slot = w * 2 + kpar;
    float* rstore  = red + slot * SLOTSTRIDE + bb0 * 9;

    // Reduce mapping: exactly 1 output per thread: j = tid>>6 (0..7), b = tid&63
    const int jr = tid >> 6;
    const int br = tid & 63;
    const float bh = b_h[c0 + jr];

    __syncthreads();

    for (int t = 0; t < SEQ; t++) {
        const float* hp = t ? (g_hs + (size_t)(t - 1) * H * B) : g_h0;

        // Early-issue token + W_xh gather (dependency-free; retires under GEMM)
        int   tk = X[br * SEQ + t];
        float wx = W_xh[(size_t)tk * H + c0 + jr];

        u64 acc[4][4];
        #pragma unroll
        for (int bi = 0; bi < 4; bi++)
            #pragma unroll
            for (int jp = 0; jp < 4; jp++) acc[bi][jp] = 0ull;

        const int kbeg = w * KC + kpar;
        const float* hb = hp + (size_t)kbeg * B + bb0;
        const float* wb = ws + kbeg * CPC;

        #pragma unroll 8
        for (int it = 0; it < KC / 2; it++) {
            float4 hv = *(const float4*)(hb + (size_t)it * 2 * B);
            ulonglong2 w0 = *(const ulonglong2*)(wb + it * 2 * CPC);      // (j0,j1),(j2,j3)
            ulonglong2 w1 = *(const ulonglong2*)(wb + it * 2 * CPC + 4);  // (j4,j5),(j6,j7)
            u64 h0 = dup2(hv.x), h1 = dup2(hv.y), h2 = dup2(hv.z), h3 = dup2(hv.w);
            ffma2(acc[0][0], h0, w0.x); ffma2(acc[0][1], h0, w0.y);
            ffma2(acc[0][2], h0, w1.x); ffma2(acc[0][3], h0, w1.y);
            ffma2(acc[1][0], h1, w0.x); ffma2(acc[1][1], h1, w0.y);
            ffma2(acc[1][2], h1, w1.x); ffma2(acc[1][3], h1, w1.y);
            ffma2(acc[2][0], h2, w0.x); ffma2(acc[2][1], h2, w0.y);
            ffma2(acc[2][2], h2, w1.x); ffma2(acc[2][3], h2, w1.y);
            ffma2(acc[3][0], h3, w0.x); ffma2(acc[3][1], h3, w0.y);
            ffma2(acc[3][2], h3, w1.x); ffma2(acc[3][3], h3, w1.y);
        }

        // Stash partials as plain floats (proven pattern; no wide stores)
        #pragma unroll
        for (int bi = 0; bi < 4; bi++) {
            float f[8];
            unpack2(acc[bi][0], f[0], f[1]);
            unpack2(acc[bi][1], f[2], f[3]);
            unpack2(acc[bi][2], f[4], f[5]);
            unpack2(acc[bi][3], f[6], f[7]);
            #pragma unroll
            for (int j = 0; j < 8; j++) rstore[bi * 9 + j] = f[j];
        }
        __syncthreads();

        // Reduce 32 slots (4 interleaved partials -> chain depth 8+2)
        {
            const float* rb = red + br * 9 + jr;
            float s0 = 0.f, s1 = 0.f, s2 = 0.f, s3 = 0.f;
            #pragma unroll
            for (int sl = 0; sl < NSLOT; sl += 4) {
                s0 += rb[(sl + 0) * SLOTSTRIDE];
                s1 += rb[(sl + 1) * SLOTSTRIDE];
                s2 += rb[(sl + 2) * SLOTSTRIDE];
                s3 += rb[(sl + 3) * SLOTSTRIDE];
            }
            float x = ((s0 + s1) + (s2 + s3)) + wx + bh;
            g_hs[(size_t)t * H * B + (size_t)(c0 + jr) * B + br] = tanh_safe(x);
        }

        grid_sync_flags(bid, (unsigned)(t + 1));
    }
}

// ---------------------------------------------------------------------------
// Output projection (unchanged, proven):
//   out[b][t][o] = sum_h hs[t][h][b] * W_hy[h][o] + b_y[o]
// ---------------------------------------------------------------------------
__global__ void __launch_bounds__(256)
rnn_output_kernel(const float* __restrict__ W_hy,
                  const float* __restrict__ b_y,
                  float* __restrict__ out) {
    __shared__ float hc[64 * 64];
    __shared__ float Wc[64 * OUTD];

    const int t   = blockIdx.x;
    const int tid = threadIdx.x;
    const int b0  = (tid & 15) * 4;
    const int o0  = (tid >> 4) * 8;

    u64 acc[4][4];
    #pragma unroll
    for (int bi = 0; bi < 4; bi++)
        #pragma unroll
        for (int op = 0; op < 4; op++) acc[bi][op] = 0ull;

    const float* hsrc = g_hs + (size_t)t * H * B;

    for (int k0 = 0; k0 < H; k0 += 64) {
        const float4* hsv = (const float4*)(hsrc + (size_t)k0 * B);
        float4* hcv = (float4*)hc;
        #pragma unroll
        for (int i = 0; i < 4; i++) hcv[tid + i * 256] = hsv[tid + i * 256];

        const float4* wsv = (const float4*)(W_hy + (size_t)k0 * OUTD);
        float4* wcv = (float4*)Wc;
        #pragma unroll
        for (int i = 0; i < 8; i++) wcv[tid + i * 256] = wsv[tid + i * 256];

        __syncthreads();

        #pragma unroll 4
        for (int k = 0; k < 64; k++) {
            float4 hv = *(const float4*)(hc + k * 64 + b0);
            ulonglong2 wq0 = *(const ulonglong2*)(Wc + k * OUTD + o0);
            ulonglong2 wq1 = *(const ulonglong2*)(Wc + k * OUTD + o0 + 4);
            u64 h0 = dup2(hv.x), h1 = dup2(hv.y), h2 = dup2(hv.z), h3 = dup2(hv.w);
            ffma2(acc[0][0], h0, wq0.x); ffma2(acc[0][1], h0, wq0.y);
            ffma2(acc[0][2], h0, wq1.x); ffma2(acc[0][3], h0, wq1.y);
            ffma2(acc[1][0], h1, wq0.x); ffma2(acc[1][1], h1, wq0.y);
            ffma2(acc[1][2], h1, wq1.x); ffma2(acc[1][3], h1, wq1.y);
            ffma2(acc[2][0], h2, wq0.x); ffma2(acc[2][1], h2, wq0.y);
            ffma2(acc[2][2], h2, wq1.x); ffma2(acc[2][3], h2, wq1.y);
            ffma2(acc[3][0], h3, wq0.x); ffma2(acc[3][1], h3, wq0.y);
            ffma2(acc[3][2], h3, wq1.x); ffma2(acc[3][3], h3, wq1.y);
        }
        __syncthreads();
    }

    float byv[8];
    #pragma unroll
    for (int oi = 0; oi < 8; oi++) byv[oi] = b_y[o0 + oi];

    #pragma unroll
    for (int bi = 0; bi < 4; bi++) {
        float f[8];
        unpack2(acc[bi][0], f[0], f[1]);
        unpack2(acc[bi][1], f[2], f[3]);
        unpack2(acc[bi][2], f[4], f[5]);
        unpack2(acc[bi][3], f[6], f[7]);
        float* dst = out + ((size_t)(b0 + bi) * SEQ + t) * OUTD + o0;
        float4 v0, v1;
        v0.x = f[0] + byv[0]; v0.y = f[1] + byv[1];
        v0.z = f[2] + byv[2]; v0.w = f[3] + byv[3];
        v1.x = f[4] + byv[4]; v1.y = f[5] + byv[5];
        v1.z = f[6] + byv[6]; v1.w = f[7] + byv[7];
        *(float4*)(dst)     = v0;
        *(float4*)(dst + 4) = v1;
    }
}

// ---------------------------------------------------------------------------
// Launch. Inputs: X[i32 64x512], W_hh[f32 1024x1024], W_xh[f32 128x1024],
// W_hy[f32 1024x128], b_h[1024], b_y[128]. Output: f32 [64][512][128].
// ---------------------------------------------------------------------------
extern "C" void kernel_launch(void* const* d_in, const int* in_sizes, int n_in,
                              void* d_out, int out_size) {
    const int*   X    = (const int*)  d_in[0];
    const float* W_hh = (const float*)d_in[1];
    const float* W_xh = (const float*)d_in[2];
    const float* W_hy = (const float*)d_in[3];
    const float* b_h  = (const float*)d_in[4];
    const float* b_y  = (const float*)d_in[5];
    float* out = (float*)d_out;

    const int smem_rnn = (H * CPC + NSLOT * SLOTSTRIDE) * (int)sizeof(float);
    cudaFuncSetAttribute(rnn_recurrence_kernel,
                         cudaFuncAttributeMaxDynamicSharedMemorySize, smem_rnn);

    rnn_reset_kernel<<<1, 128>>>();
    rnn_recurrence_kernel<<<G, NT, smem_rnn>>>(X, W_hh, W_xh, b_h);
    rnn_output_kernel<<<SEQ, 256>>>(W_hy, b_y, out);
}

// round 13
// speedup vs baseline: 1.7478x; 1.7478x over previous
#include <cuda_runtime.h>
#include <math.h>

// Problem constants
#define B    64
#define SEQ  512
#define H    1024
#define OUTD 128

// Fused config: 128 recurrence CTAs (proven R9 design) + 20 epilogue workers.
#define G    128           // recurrence CTAs (barrier participants)
#define NEP  20            // epilogue worker CTAs (read-only pollers)
#define GT   (G + NEP)     // 148 = SM count -> all co-resident, 1 CTA/SM
#define CPC  8             // columns of W_hh per CTA (H / G)
#define NT   512           // 16 warps -> 4 per SMSP
#define NW   16
#define KC   (H / NW)      // 64 k per warp (lane k-parity -> 32 iters)
#define NSLOT (2 * NW)     // 32 partial slots (warp x k-parity)
#define SLOTSTRIDE 577     // 64*9 + 1 pad (float stores only)

static_assert(G * CPC == H, "partition");

typedef unsigned long long u64;

// Scratch (device globals: allocation-free rule). Zero-initialized at load.
__device__ float g_hs[(size_t)SEQ * H * B];  // hidden states [t][h][b]
__device__ float g_h0[H * B];                // initial h = 0 (never written)
__device__ unsigned g_arrive;
__device__ volatile unsigned g_release;

// ---------------------------------------------------------------------------
// Packed f32x2 helpers (Blackwell FFMA2)
// ---------------------------------------------------------------------------
__device__ __forceinline__ u64 dup2(float x) {
    u64 r; unsigned u = __float_as_uint(x);
    asm("mov.b64 %0, {%1, %2};" : "=l"(r) : "r"(u), "r"(u));
    return r;
}
__device__ __forceinline__ void ffma2(u64& d, u64 a, u64 b) {
    asm("fma.rn.f32x2 %0, %1, %2, %3;" : "=l"(d) : "l"(a), "l"(b), "l"(d));
}
__device__ __forceinline__ void unpack2(u64 v, float& x, float& y) {
    unsigned lo, hi;
    asm("mov.b64 {%0, %1}, %2;" : "=r"(lo), "=r"(hi) : "l"(v));
    x = __uint_as_float(lo); y = __uint_as_float(hi);
}

__device__ __forceinline__ float tanh_safe(float x) {
    float ax = fabsf(x);
    float e  = __expf(2.0f * ax);
    float r  = 1.0f - 2.0f / (e + 1.0f);
    return copysignf(r, x);
}

// ---------------------------------------------------------------------------
// Grid barrier among the 128 recurrence CTAs — exact R3/R9-proven pattern.
// Workers never touch g_arrive; they only read g_release.
// ---------------------------------------------------------------------------
__device__ __forceinline__ void grid_sync() {
    __syncthreads();
    if (threadIdx.x == 0) {
        __threadfence();                       // publish this CTA's g_hs writes
        unsigned gen = g_release;
        if (atomicAdd(&g_arrive, 1u) == G - 1u) {
            g_arrive = 0;
            __threadfence();
            g_release = gen + 1u;              // sole writer for this generation
        } else {
            while (g_release == gen) { }
        }
        __threadfence();                       // acquire other CTAs' writes
    }
    __syncthreads();
}

// ---------------------------------------------------------------------------
// Reset barrier state each launch (graph replays must start from zero so the
// workers' absolute t+1 thresholds are valid).
// ---------------------------------------------------------------------------
__global__ void rnn_reset_kernel() {
    if (threadIdx.x == 0) { g_arrive = 0u; *(unsigned*)&g_release = 0u; }
}

// ---------------------------------------------------------------------------
// Fused persistent kernel.
//  bid <  G : recurrence (R9-proven body). h_t = tanh(h_{t-1}@W_hh + x_t + b).
//  bid >= G : epilogue worker. For t = bid-G, t+NEP, ...: wait g_release>=t+1,
//             then out[:,t,:] = hs[t] @ W_hy + b_y with 512-thread split-k.
//             Thread pair (tl, tl+256) shares one (b,o) tile: tl = tid & 255.
// ---------------------------------------------------------------------------
__global__ void __launch_bounds__(NT, 1)
rnn_fused_kernel(const int* __restrict__ X,
                 const float* __restrict__ W_hh,
                 const float* __restrict__ W_xh,
                 const float* __restrict__ W_hy,
                 const float* __restrict__ b_h,
                 const float* __restrict__ b_y,
                 float* __restrict__ out) {
    extern __shared__ float sm[];
    const int tid = threadIdx.x;
    const int bid = blockIdx.x;

    if (bid < G) {
        // ================= recurrence role (R9 verbatim) =================
        float* ws  = sm;                       // [H][CPC]    32 KB
        float* red = sm + H * CPC;             // [32][577]   ~72 KB

        const int c0 = bid * CPC;

        for (int i = tid; i < H * CPC; i += NT) {
            int k = i >> 3, j = i & 7;
            ws[i] = W_hh[(size_t)k * H + c0 + j];
        }

        const int w    = tid >> 5;
        const int lane = tid & 31;
        const int b4   = lane & 15;
        const int kpar = lane >> 4;
        const int bb0  = b4 * 4;
        const int slot = w * 2 + kpar;
        float* rstore  = red + slot * SLOTSTRIDE + bb0 * 9;

        const int jr = tid >> 6;
        const int br = tid & 63;
        const float bh = b_h[c0 + jr];

        __syncthreads();

        for (int t = 0; t < SEQ; t++) {
            const float* hp = t ? (g_hs + (size_t)(t - 1) * H * B) : g_h0;

            int   tk = X[br * SEQ + t];
            float wx = W_xh[(size_t)tk * H + c0 + jr];

            u64 acc[4][4];
            #pragma unroll
            for (int bi = 0; bi < 4; bi++)
                #pragma unroll
                for (int jp = 0; jp < 4; jp++) acc[bi][jp] = 0ull;

            const int kbeg = w * KC + kpar;
            const float* hb = hp + (size_t)kbeg * B + bb0;
            const float* wb = ws + kbeg * CPC;

            #pragma unroll 8
            for (int it = 0; it < KC / 2; it++) {
                float4 hv = *(const float4*)(hb + (size_t)it * 2 * B);
                ulonglong2 w0 = *(const ulonglong2*)(wb + it * 2 * CPC);
                ulonglong2 w1 = *(const ulonglong2*)(wb + it * 2 * CPC + 4);
                u64 h0 = dup2(hv.x), h1 = dup2(hv.y), h2 = dup2(hv.z), h3 = dup2(hv.w);
                ffma2(acc[0][0], h0, w0.x); ffma2(acc[0][1], h0, w0.y);
                ffma2(acc[0][2], h0, w1.x); ffma2(acc[0][3], h0, w1.y);
                ffma2(acc[1][0], h1, w0.x); ffma2(acc[1][1], h1, w0.y);
                ffma2(acc[1][2], h1, w1.x); ffma2(acc[1][3], h1, w1.y);
                ffma2(acc[2][0], h2, w0.x); ffma2(acc[2][1], h2, w0.y);
                ffma2(acc[2][2], h2, w1.x); ffma2(acc[2][3], h2, w1.y);
                ffma2(acc[3][0], h3, w0.x); ffma2(acc[3][1], h3, w0.y);
                ffma2(acc[3][2], h3, w1.x); ffma2(acc[3][3], h3, w1.y);
            }

            #pragma unroll
            for (int bi = 0; bi < 4; bi++) {
                float f[8];
                unpack2(acc[bi][0], f[0], f[1]);
                unpack2(acc[bi][1], f[2], f[3]);
                unpack2(acc[bi][2], f[4], f[5]);
                unpack2(acc[bi][3], f[6], f[7]);
                #pragma unroll
                for (int j = 0; j < 8; j++) rstore[bi * 9 + j] = f[j];
            }
            __syncthreads();

            {
                const float* rb = red + br * 9 + jr;
                float s0 = 0.f, s1 = 0.f, s2 = 0.f, s3 = 0.f;
                #pragma unroll
                for (int sl = 0; sl < NSLOT; sl += 4) {
                    s0 += rb[(sl + 0) * SLOTSTRIDE];
                    s1 += rb[(sl + 1) * SLOTSTRIDE];
                    s2 += rb[(sl + 2) * SLOTSTRIDE];
                    s3 += rb[(sl + 3) * SLOTSTRIDE];
                }
                float x = ((s0 + s1) + (s2 + s3)) + wx + bh;
                g_hs[(size_t)t * H * B + (size_t)(c0 + jr) * B + br] = tanh_safe(x);
            }

            grid_sync();
        }
    } else {
        // ================= epilogue worker role =================
        float* hc = sm;             // [k64][b64]  16 KB
        float* Wc = sm + 64 * 64;   // [k64][o128] 32 KB

        const int tl = tid & 255;          // tile lane: pair (tl, tl+256)
        const int b0 = (tl & 15) * 4;      // batch tile (0..60)
        const int o0 = (tl >> 4) * 8;      // output tile (0..120)
        const int kh = (tid >> 8) * 32;    // k-half: 0 or 32

        float byv[8];
        #pragma unroll
        for (int oi = 0; oi < 8; oi++) byv[oi] = b_y[o0 + oi];

        for (int t = bid - G; t < SEQ; t += NEP) {
            // Wait (read-only, 1 thread, backoff) until step t is published.
            if (tid == 0) {
                while (g_release < (unsigned)(t + 1)) __nanosleep(128);
                __threadfence();   // acquire producers' g_hs writes
            }
            __syncthreads();

            u64 acc[4][4];
            #pragma unroll
            for (int bi = 0; bi < 4; bi++)
                #pragma unroll
                for (int op = 0; op < 4; op++) acc[bi][op] = 0ull;

            const float* hsrc = g_hs + (size_t)t * H * B;

            for (int k0 = 0; k0 < H; k0 += 64) {
                const float4* hsv = (const float4*)(hsrc + (size_t)k0 * B);
                float4* hcv = (float4*)hc;
                #pragma unroll
                for (int i = 0; i < 2; i++) hcv[tid + i * 512] = hsv[tid + i * 512];

                const float4* wsv = (const float4*)(W_hy + (size_t)k0 * OUTD);
                float4* wcv = (float4*)Wc;
                #pragma unroll
                for (int i = 0; i < 4; i++) wcv[tid + i * 512] = wsv[tid + i * 512];

                __syncthreads();

                #pragma unroll 4
                for (int kk = 0; kk < 32; kk++) {
                    int k = kh + kk;
                    float4 hv = *(const float4*)(hc + k * 64 + b0);
                    ulonglong2 wq0 = *(const ulonglong2*)(Wc + k * OUTD + o0);
                    ulonglong2 wq1 = *(const ulonglong2*)(Wc + k * OUTD + o0 + 4);
                    u64 h0 = dup2(hv.x), h1 = dup2(hv.y), h2 = dup2(hv.z), h3 = dup2(hv.w);
                    ffma2(acc[0][0], h0, wq0.x); ffma2(acc[0][1], h0, wq0.y);
                    ffma2(acc[0][2], h0, wq1.x); ffma2(acc[0][3], h0, wq1.y);
                    ffma2(acc[1][0], h1, wq0.x); ffma2(acc[1][1], h1, wq0.y);
                    ffma2(acc[1][2], h1, wq1.x); ffma2(acc[1][3], h1, wq1.y);
                    ffma2(acc[2][0], h2, wq0.x); ffma2(acc[2][1], h2, wq0.y);
                    ffma2(acc[2][2], h2, wq1.x); ffma2(acc[2][3], h2, wq1.y);
                    ffma2(acc[3][0], h3, wq0.x); ffma2(acc[3][1], h3, wq0.y);
                    ffma2(acc[3][2], h3, wq1.x); ffma2(acc[3][3], h3, wq1.y);
                }
                __syncthreads();
            }

            // Combine the two k-halves through smem (reuse hc region).
            {
                float* stage = hc;   // 256 slots x 33 floats = 33 KB (hc+Wc reused)
                if (tid >= 256) {
                    float* dstp = stage + tl * 33;
                    #pragma unroll
                    for (int bi = 0; bi < 4; bi++) {
                        float f[8];
                        unpack2(acc[bi][0], f[0], f[1]);
                        unpack2(acc[bi][1], f[2], f[3]);
                        unpack2(acc[bi][2], f[4], f[5]);
                        unpack2(acc[bi][3], f[6], f[7]);
                        #pragma unroll
                        for (int oi = 0; oi < 8; oi++) dstp[bi * 8 + oi] = f[oi];
                    }
                }
                __syncthreads();
                if (tid < 256) {
                    const float* srcp = stage + tl * 33;
                    #pragma unroll
                    for (int bi = 0; bi < 4; bi++) {
                        float f[8];
                        unpack2(acc[bi][0], f[0], f[1]);
                        unpack2(acc[bi][1], f[2], f[3]);
                        unpack2(acc[bi][2], f[4], f[5]);
                        unpack2(acc[bi][3], f[6], f[7]);
                        float* dst = out + ((size_t)(b0 + bi) * SEQ + t) * OUTD + o0;
                        float4 v0, v1;
                        v0.x = f[0] + srcp[bi*8+0] + byv[0];
                        v0.y = f[1] + srcp[bi*8+1] + byv[1];
                        v0.z = f[2] + srcp[bi*8+2] + byv[2];
                        v0.w = f[3] + srcp[bi*8+3] + byv[3];
                        v1.x = f[4] + srcp[bi*8+4] + byv[4];
                        v1.y = f[5] + srcp[bi*8+5] + byv[5];
                        v1.z = f[6] + srcp[bi*8+6] + byv[6];
                        v1.w = f[7] + srcp[bi*8+7] + byv[7];
                        *(float4*)(dst)     = v0;
                        *(float4*)(dst + 4) = v1;
                    }
                }
                __syncthreads();   // stage dead before next t reuses hc
            }
        }
    }
}

// ---------------------------------------------------------------------------
// Launch. Inputs: X[i32 64x512], W_hh[f32 1024x1024], W_xh[f32 128x1024],
// W_hy[f32 1024x128], b_h[1024], b_y[128]. Output: f32 [64][512][128].
// ---------------------------------------------------------------------------
extern "C" void kernel_launch(void* const* d_in, const int* in_sizes, int n_in,
                              void* d_out, int out_size) {
    const int*   X    = (const int*)  d_in[0];
    const float* W_hh = (const float*)d_in[1];
    const float* W_xh = (const float*)d_in[2];
    const float* W_hy = (const float*)d_in[3];
    const float* b_h  = (const float*)d_in[4];
    const float* b_y  = (const float*)d_in[5];
    float* out = (float*)d_out;

    const int smem_rec = (H * CPC + NSLOT * SLOTSTRIDE) * (int)sizeof(float);
    const int smem_epi = (64 * 64 + 64 * OUTD) * (int)sizeof(float);
    const int smem = smem_rec > smem_epi ? smem_rec : smem_epi;

    cudaFuncSetAttribute(rnn_fused_kernel,
                         cudaFuncAttributeMaxDynamicSharedMemorySize, smem);

    rnn_reset_kernel<<<1, 32>>>();
    rnn_fused_kernel<<<GT, NT, smem>>>(X, W_hh, W_xh, W_hy, b_h, b_y, out);
}